// round 7
// baseline (speedup 1.0000x reference)
#include <cuda_runtime.h>
#include <cstdint>
#include <cstddef>

#define BS      64
#define NVAL    25200
#define KCAND   512
#define MAXDET  300
#define CONF_T  0.25f
#define IOU_T   0.45f
#define MAX_WH  7680.0f

typedef unsigned long long u64;

// ---- static device scratch (no allocation anywhere) ----
__device__ u64          g_keys[(size_t)BS * NVAL];        // 12.9 MB
__device__ unsigned int g_hist[BS][256];                  // zero-init; self-resetting

// ---------------------------------------------------------------------------
// K1: scores -> 64-bit sortable keys + per-image MSB histogram.
//     Warp-aggregated histogram atomics (bins heavily skewed).
// ---------------------------------------------------------------------------
__global__ void score_kernel(const float* __restrict__ pred) {
    int b = blockIdx.y;
    int i = blockIdx.x * blockDim.x + threadIdx.x;
    __shared__ unsigned int sh[256];
    if (threadIdx.x < 256) sh[threadIdx.x] = 0u;
    __syncthreads();

    bool act = (i < NVAL);
    unsigned int am = __ballot_sync(0xffffffffu, act);
    if (act) {
        const float4* p = (const float4*)(pred + ((size_t)b * NVAL + i) * 8);
        float4 c = p[1];                           // obj, cls0, cls1, cls2
        float s0 = __fmul_rn(c.x, c.y);
        float s1 = __fmul_rn(c.x, c.z);
        float s2 = __fmul_rn(c.x, c.w);
        float best = s0;
        if (s1 > best) best = s1;
        if (s2 > best) best = s2;
        unsigned int bits = __float_as_uint(best); // scores >= 0 -> monotonic
        g_keys[(size_t)b * NVAL + i] =
            ((u64)bits << 32) | (0xFFFFFFFFu - (unsigned int)i);
        unsigned int bin = bits >> 24;
        unsigned int mm = __match_any_sync(am, bin);
        if ((threadIdx.x & 31) == (__ffs(mm) - 1))
            atomicAdd(&sh[bin], (unsigned int)__popc(mm));
    }
    __syncthreads();
    if (threadIdx.x < 256 && sh[threadIdx.x])
        atomicAdd(&g_hist[b][threadIdx.x], sh[threadIdx.x]);
}

// ---------------------------------------------------------------------------
// K2 (fused): radix top-512 + bitonic sort + IoU mask (smem) + sparse greedy
//             scan + pack. One block / image, 1024 threads, ~54 KB smem.
// ---------------------------------------------------------------------------
extern __shared__ unsigned char smdyn[];

__global__ void __launch_bounds__(1024, 1)
fused_kernel(const float* __restrict__ pred, float* __restrict__ out) {
    const int b   = blockIdx.x;
    const int tid = threadIdx.x;

    u64*   tm     = (u64*)(smdyn);                     // [8*KCAND]  32768 B
    u64*   keysS  = (u64*)(smdyn + 32768);             // [KCAND]     4096 B
    float* sx1    = (float*)(smdyn + 36864);
    float* sy1    = sx1 + KCAND;
    float* sx2    = sy1 + KCAND;
    float* sy2    = sx2 + KCAND;
    float* sar    = sy2 + KCAND;
    float* scoreS = sar + KCAND;
    int*   cidS   = (int*)(smdyn + 36864 + 6 * KCAND * 4);
    int*   topiS  = cidS + KCAND;

    __shared__ unsigned int hist[257];
    __shared__ u64 s_prefix;
    __shared__ int s_shift, s_done, s_need, s_nv;
    __shared__ unsigned int s_cnt;
    __shared__ unsigned int nz32[16], conf32[16], valid32[16];

    const u64* keys = g_keys + (size_t)b * NVAL;

    // ================= radix select: exact top-512 =================
    if (tid < 256) {
        hist[tid] = g_hist[b][tid];      // pass-1 hist (from score_kernel)
        g_hist[b][tid] = 0u;             // reset for next graph replay
    }
    if (tid == 0) { hist[256] = 0u; s_done = 0; s_need = KCAND;
                    s_prefix = 0ull; s_shift = 64; }
    __syncthreads();

    for (int lvl = 0; lvl < 8; ++lvl) {      // bounded: shift 64 -> 0
        // parallel suffix sum: hist[t] <- sum_{u>=t} hist[u]
        #pragma unroll
        for (int off = 1; off < 256; off <<= 1) {
            unsigned v = 0;
            if (tid < 256)
                v = hist[tid] + ((tid + off < 256) ? hist[tid + off] : 0u);
            __syncthreads();
            if (tid < 256) hist[tid] = v;
            __syncthreads();
        }
        // RACE FIX: snapshot need in ALL threads, barrier, THEN select+write.
        const int need = s_need;
        __syncthreads();
        // unique threshold bin: sfx[bin] >= need && sfx[bin+1] < need
        if (tid < 256) {
            unsigned sfx = hist[tid], sfx1 = hist[tid + 1];
            if ((int)sfx >= need && (int)sfx1 < need) {
                int hbin     = (int)(sfx - sfx1);
                int need_new = need - (int)sfx1;
                s_prefix = (s_prefix << 8) | (unsigned int)tid;
                s_shift -= 8;
                s_need = need_new;
                if (hbin == need_new || s_shift == 0) s_done = 1;
            }
        }
        __syncthreads();
        if (s_done) break;
        if (tid < 256) hist[tid] = 0u;
        __syncthreads();
        {
            u64 pf = s_prefix;
            int sh = s_shift;
            for (int i = tid; i < NVAL; i += 1024) {
                u64 kk = keys[i];
                if ((kk >> sh) == pf)
                    atomicAdd(&hist[(unsigned int)(kk >> (sh - 8)) & 255u], 1u);
            }
        }
        __syncthreads();
    }

    if (tid == 0) s_cnt = 0u;
    __syncthreads();
    {
        u64 pf = s_prefix;
        int sh = s_shift;
        for (int i = tid; i < NVAL; i += 1024) {
            u64 kk = keys[i];
            if ((kk >> sh) >= pf) {
                unsigned int pos = atomicAdd(&s_cnt, 1u);
                keysS[pos] = kk;
            }
        }
    }
    __syncthreads();

    // ================= bitonic sort descending (keys distinct) =================
    for (int kk = 2; kk <= KCAND; kk <<= 1) {
        for (int j = kk >> 1; j > 0; j >>= 1) {
            if (tid < KCAND) {
                int ixj = tid ^ j;
                if (ixj > tid) {
                    bool dirDesc = ((tid & kk) == 0);
                    u64 a = keysS[tid], c = keysS[ixj];
                    bool sw = dirDesc ? (a < c) : (a > c);
                    if (sw) { keysS[tid] = c; keysS[ixj] = a; }
                }
            }
            __syncthreads();
        }
    }

    // ================= extract candidate data into smem =================
    if (tid < KCAND) {
        u64 kk = keysS[tid];
        int   idx = (int)(0xFFFFFFFFu - (unsigned int)kk);
        float sc  = __uint_as_float((unsigned int)(kk >> 32));
        const float4* p = (const float4*)(pred + ((size_t)b * NVAL + idx) * 8);
        float4 a = p[0];                 // cx, cy, w, h
        float4 c = p[1];                 // obj, cls0..2
        float s0 = __fmul_rn(c.x, c.y);
        float s1 = __fmul_rn(c.x, c.z);
        float s2 = __fmul_rn(c.x, c.w);
        int cid = 0; float bv = s0;
        if (s1 > bv) { bv = s1; cid = 1; }
        if (s2 > bv) { bv = s2; cid = 2; }
        float hw  = __fmul_rn(a.z, 0.5f), hh = __fmul_rn(a.w, 0.5f);
        float bx1 = __fsub_rn(a.x, hw),  by1 = __fsub_rn(a.y, hh);
        float bx2 = __fadd_rn(a.x, hw),  by2 = __fadd_rn(a.y, hh);
        float off = __fmul_rn((float)cid, MAX_WH);
        float X1 = __fadd_rn(bx1, off), Y1 = __fadd_rn(by1, off);
        float X2 = __fadd_rn(bx2, off), Y2 = __fadd_rn(by2, off);
        sx1[tid] = X1; sy1[tid] = Y1; sx2[tid] = X2; sy2[tid] = Y2;
        sar[tid]    = __fmul_rn(__fsub_rn(X2, X1), __fsub_rn(Y2, Y1));
        scoreS[tid] = sc;
        cidS[tid]   = cid;
        topiS[tid]  = idx;
    }
    __syncthreads();

    // ================= IoU suppression mask (smem, word-major) =================
    {
        const int i    = tid & (KCAND - 1);
        const int wlo  = (tid >> 9) << 2;
        const int ic   = i >> 6;
        float ax1 = sx1[i], ay1 = sy1[i], ax2 = sx2[i], ay2 = sy2[i], aa = sar[i];
        #pragma unroll
        for (int dw = 0; dw < 4; ++dw) {
            int w = wlo + dw;
            u64 word = 0ull;
            if (w >= ic) {                         // below-diagonal words all zero
                int jbase = w << 6;
                #pragma unroll 4
                for (int bb = 0; bb < 64; ++bb) {
                    int j = jbase + bb;
                    float ltx = fmaxf(ax1, sx1[j]), lty = fmaxf(ay1, sy1[j]);
                    float rbx = fminf(ax2, sx2[j]), rby = fminf(ay2, sy2[j]);
                    float iw = fmaxf(__fsub_rn(rbx, ltx), 0.0f);
                    float ih = fmaxf(__fsub_rn(rby, lty), 0.0f);
                    float inter = __fmul_rn(iw, ih);
                    if ((j > i) && (inter > 0.0f)) {   // inter==0 -> iou==0 exactly
                        float denom = __fadd_rn(__fsub_rn(__fadd_rn(aa, sar[j]), inter), 1e-7f);
                        if (__fdiv_rn(inter, denom) > IOU_T) word |= (1ull << bb);
                    }
                }
            }
            tm[w * KCAND + i] = word;
        }
    }
    __syncthreads();

    // ================= nonzero-row + conf bitmaps (ballots) =================
    if (tid < KCAND) {
        u64 o = tm[tid]            | tm[KCAND     + tid] |
                tm[2*KCAND + tid]  | tm[3*KCAND   + tid] |
                tm[4*KCAND + tid]  | tm[5*KCAND   + tid] |
                tm[6*KCAND + tid]  | tm[7*KCAND   + tid];
        unsigned bnz = __ballot_sync(0xffffffffu, o != 0ull);
        unsigned bcf = __ballot_sync(0xffffffffu, scoreS[tid] > CONF_T);
        if ((tid & 31) == 0) { nz32[tid >> 5] = bnz; conf32[tid >> 5] = bcf; }
    }
    __syncthreads();

    // ====== serial greedy over nonzero rows only (zero rows can't change sup) ======
    if (tid == 0) {
        u64 sup[8] = {0,0,0,0,0,0,0,0};
        u64 nz[8];
        #pragma unroll
        for (int q = 0; q < 8; ++q)
            nz[q] = (u64)nz32[2*q] | ((u64)nz32[2*q + 1] << 32);
        #pragma unroll
        for (int w = 0; w < 8; ++w) {
            u64 x = nz[w] & ~sup[w];
            while (x) {
                int bb = __ffsll((long long)x) - 1;
                int i = (w << 6) + bb;
                #pragma unroll
                for (int q = 0; q < 8; ++q) sup[q] |= tm[q * KCAND + i];
                u64 above = (bb == 63) ? 0ull : (~0ull << (bb + 1));
                x = nz[w] & ~sup[w] & above;   // 'above' guarantees progress
            }
        }
        int nv = 0;
        #pragma unroll
        for (int w = 0; w < 8; ++w) {
            u64 conf = (u64)conf32[2*w] | ((u64)conf32[2*w + 1] << 32);
            u64 valid = (~sup[w]) & conf;
            if (w == 0) valid |= 1ull;     // index 0: never suppressed, rank 1
            valid32[2*w]     = (unsigned int)valid;
            valid32[2*w + 1] = (unsigned int)(valid >> 32);
            nv += __popcll(valid);
        }
        s_nv = nv;
    }
    __syncthreads();

    // ====== parallel pack: tid-th valid (asc) or (tid-nv)-th invalid (asc) ======
    if (tid < MAXDET) {
        int nv = s_nv;
        bool isv = tid < nv;
        int r = isv ? tid : tid - nv;
        int k = -1;
        #pragma unroll
        for (int wi = 0; wi < 16; ++wi) {
            unsigned wv = valid32[wi];
            if (!isv) wv = ~wv;
            int c = __popc(wv);
            if (k < 0) {
                if (r < c) k = wi * 32 + __fns(wv, 0, r + 1);
                else       r -= c;
            }
        }
        int gi = topiS[k];
        float b0 = 0.f, b1 = 0.f, b2 = 0.f, b3 = 0.f, sc = 0.f;
        if (isv) {
            const float4* p = (const float4*)(pred + ((size_t)b * NVAL + gi) * 8);
            float4 a = p[0];
            float hw = __fmul_rn(a.z, 0.5f), hh = __fmul_rn(a.w, 0.5f);
            b0 = __fsub_rn(a.x, hw); b1 = __fsub_rn(a.y, hh);
            b2 = __fadd_rn(a.x, hw); b3 = __fadd_rn(a.y, hh);
            sc = scoreS[k];
        }
        const size_t scoresOff = (size_t)BS * MAXDET * 4;
        const size_t clsOff    = scoresOff + (size_t)BS * MAXDET;
        const size_t idsOff    = clsOff    + (size_t)BS * MAXDET;
        const size_t valOff    = idsOff    + (size_t)BS * MAXDET;
        size_t rr = (size_t)b * MAXDET + tid;
        out[rr * 4 + 0] = b0;
        out[rr * 4 + 1] = b1;
        out[rr * 4 + 2] = b2;
        out[rr * 4 + 3] = b3;
        out[scoresOff + rr] = sc;
        out[clsOff + rr] = (float)cidS[k];     // NOT zeroed for pads (ref semantics)
        out[idsOff + rr] = (float)(gi / 3);    // NOT zeroed for pads (ref semantics)
        out[valOff + rr] = isv ? 1.0f : 0.0f;
    }
}

// ---------------------------------------------------------------------------
extern "C" void kernel_launch(void* const* d_in, const int* in_sizes, int n_in,
                              void* d_out, int out_size) {
    (void)in_sizes; (void)n_in; (void)out_size;
    const float* pred = (const float*)d_in[0];
    float* out = (float*)d_out;

    score_kernel<<<dim3((NVAL + 1023) / 1024, BS), 1024>>>(pred);
    cudaFuncSetAttribute(fused_kernel,
                         cudaFuncAttributeMaxDynamicSharedMemorySize, 53248);
    fused_kernel<<<BS, 1024, 53248>>>(pred, out);
}